// round 14
// baseline (speedup 1.0000x reference)
#include <cuda_runtime.h>
#include <cstdint>

// ---------------------------------------------------------------------------
// StandGCN2: 2-layer GCN. N<=100096, F=128 -> 128 -> 64.
//   dinv = rsqrt(1+indeg)
//   hs1  = x @ W1                      (GEMM1, f32x2, independent of preproc)
//   agg1[d] = dinv[d]*hs1[d] + sum dinv[s]*hs1[s]   (bucketed smem scatter)
//   h1   = relu(dinv*agg1 + b1)        (fused into GEMM2 A-load)
//   hs2  = dinv[r]*(h1 @ W2)           (GEMM2 fp32, R10 version)
//   OUT[d] = dinv[d]*(hs2[d]+sum hs2[src]) + b2
// Preprocessing overlapped with GEMM1 on a side stream (R10 structure).
// NEW vs R10: edge kernels use 2 warps per 16-node bucket (feature halves)
// to double gather MLP; per-feature accumulation order unchanged.
// ---------------------------------------------------------------------------

#define MAXN 100096
#define MAXB (MAXN / 16)
#define MAXE 1200000

__device__ float g_deg[MAXN];
__device__ float g_dinv[MAXN];
__device__ __align__(16) float g_hs1[(size_t)MAXN * 128];
__device__ __align__(16) float g_agg1[(size_t)MAXN * 128];
__device__ __align__(16) float g_hs2[(size_t)MAXN * 64];

__device__ int g_esrc[MAXE];
__device__ int g_edst[MAXE];
__device__ int g_bstart[MAXB + 1];
__device__ int g_bcur[MAXB];

typedef unsigned long long u64;

#define FMA2(d, a, b) \
    asm("fma.rn.f32x2 %0, %1, %2, %3;" : "=l"(d) : "l"(a), "l"(b), "l"(d))
#define DUP2(d, x) \
    asm("mov.b64 %0, {%1, %1};" : "=l"(d) : "r"(__float_as_uint(x)))

__device__ __forceinline__ float2 u64_as_f2(u64 v) {
    float2 r;
    asm("mov.b64 {%0, %1}, %2;" : "=f"(r.x), "=f"(r.y) : "l"(v));
    return r;
}

// ---------------------------------------------------------------------------
// Preprocessing (side stream)
// ---------------------------------------------------------------------------
__global__ void k_init(int n, int nb) {
    int i = blockIdx.x * blockDim.x + threadIdx.x;
    if (i < n) g_deg[i] = 1.0f;
    if (i < nb) g_bcur[i] = 0;
}

__global__ void k_count(const int* __restrict__ dst, int e) {
    int i = blockIdx.x * blockDim.x + threadIdx.x;
    if (i >= e) return;
    int d = dst[i];
    atomicAdd(&g_deg[d], 1.0f);
    atomicAdd(&g_bcur[d >> 4], 1);
}

__global__ void k_dinv(int n) {
    int i = blockIdx.x * blockDim.x + threadIdx.x;
    if (i < n) g_dinv[i] = rsqrtf(g_deg[i]);
}

// Single-block warp-shuffle exclusive scan over <=8192 bucket counts.
__global__ void k_scan(int nb) {
    __shared__ int wsum[32];
    const int t = threadIdx.x;
    const int per = (nb + 1023) / 1024;  // <= 8
    const int base = t * per;
    int v[8];
    int s = 0;
#pragma unroll
    for (int i = 0; i < 8; i++) {
        int idx = base + i;
        int x = (i < per && idx < nb) ? g_bcur[idx] : 0;
        v[i] = s;
        s += x;
    }
    const int lane = t & 31, w = t >> 5;
    int ps = s;
#pragma unroll
    for (int o = 1; o < 32; o <<= 1) {
        int y = __shfl_up_sync(0xFFFFFFFFu, ps, o);
        if (lane >= o) ps += y;
    }
    if (lane == 31) wsum[w] = ps;
    __syncthreads();
    if (w == 0) {
        int ws = wsum[lane];
#pragma unroll
        for (int o = 1; o < 32; o <<= 1) {
            int y = __shfl_up_sync(0xFFFFFFFFu, ws, o);
            if (lane >= o) ws += y;
        }
        wsum[lane] = ws;
    }
    __syncthreads();
    int excl = ps - s + (w > 0 ? wsum[w - 1] : 0);
#pragma unroll
    for (int i = 0; i < 8; i++) {
        int idx = base + i;
        if (i < per && idx < nb) {
            int e = excl + v[i];
            g_bstart[idx] = e;
            g_bcur[idx] = e;
        }
    }
    if (t == 1023) g_bstart[nb] = excl + s;
}

__global__ void k_sort(const int* __restrict__ src, const int* __restrict__ dst,
                       int e) {
    int i = blockIdx.x * blockDim.x + threadIdx.x;
    if (i >= e) return;
    int s = src[i], d = dst[i];
    int pos = atomicAdd(&g_bcur[d >> 4], 1);
    g_esrc[pos] = s;
    g_edst[pos] = d;
}

// ---------------------------------------------------------------------------
// GEMM1: hs1 = X @ W1 (raw),  X:[M,128], W1:[128,128]
// Block 128x128, 256 threads, 8x8 microtile via f32x2, double-buffered.
// (Frozen; measured at the practical f32x2+smem bound.)
// ---------------------------------------------------------------------------
__global__ __launch_bounds__(256, 2) void k_gemm1(const float* __restrict__ X,
                                                  const float* __restrict__ W,
                                                  int M) {
    __shared__ float As[2][16][128];
    __shared__ float Bs[2][16][128];

    const int tid = threadIdx.x;
    const int row0 = blockIdx.x * 128;
    const int tx = tid & 15, ty = tid >> 4;
    const int r0 = ty * 8, c0 = tx * 8;

    u64 acc[4][8];
#pragma unroll
    for (int i = 0; i < 4; i++)
#pragma unroll
        for (int j = 0; j < 8; j++) acc[i][j] = 0ull;

    float4 ra[2], rb[2];

    auto ldg = [&](int kc) {
#pragma unroll
        for (int l = 0; l < 2; l++) {
            int i = tid + l * 256;
            int r = i & 127, q4 = i >> 7;
            int gr = row0 + r;
            ra[l] = make_float4(0.f, 0.f, 0.f, 0.f);
            if (gr < M)
                ra[l] = reinterpret_cast<const float4*>(X)[(size_t)gr * 32 + kc * 4 + q4];
            rb[l] = reinterpret_cast<const float4*>(W)[(size_t)kc * 512 + i];
        }
    };
    auto sts = [&](int buf) {
#pragma unroll
        for (int l = 0; l < 2; l++) {
            int i = tid + l * 256;
            int r = i & 127, q4 = i >> 7;
            As[buf][q4 * 4 + 0][r] = ra[l].x;
            As[buf][q4 * 4 + 1][r] = ra[l].y;
            As[buf][q4 * 4 + 2][r] = ra[l].z;
            As[buf][q4 * 4 + 3][r] = ra[l].w;
            reinterpret_cast<float4*>(&Bs[buf][0][0])[i] = rb[l];
        }
    };

    ldg(0);
    sts(0);
    ldg(1);
    __syncthreads();

    for (int kc = 0; kc < 8; kc++) {
        const int cur = kc & 1;
        if (kc + 1 < 8) sts((kc + 1) & 1);
        if (kc + 2 < 8) ldg(kc + 2);
#pragma unroll
        for (int k = 0; k < 16; k++) {
            ulonglong2 a01 = *reinterpret_cast<const ulonglong2*>(&As[cur][k][r0]);
            ulonglong2 a23 = *reinterpret_cast<const ulonglong2*>(&As[cur][k][r0 + 4]);
            float4 bl = *reinterpret_cast<const float4*>(&Bs[cur][k][c0]);
            float4 bh = *reinterpret_cast<const float4*>(&Bs[cur][k][c0 + 4]);
            u64 ap[4] = {a01.x, a01.y, a23.x, a23.y};
            u64 bb[8];
            DUP2(bb[0], bl.x); DUP2(bb[1], bl.y); DUP2(bb[2], bl.z); DUP2(bb[3], bl.w);
            DUP2(bb[4], bh.x); DUP2(bb[5], bh.y); DUP2(bb[6], bh.z); DUP2(bb[7], bh.w);
#pragma unroll
            for (int rp = 0; rp < 4; rp++)
#pragma unroll
                for (int j = 0; j < 8; j++) FMA2(acc[rp][j], ap[rp], bb[j]);
        }
        __syncthreads();
    }

#pragma unroll
    for (int rp = 0; rp < 4; rp++) {
        int gre = row0 + r0 + 2 * rp;
        float2 p[8];
#pragma unroll
        for (int j = 0; j < 8; j++) p[j] = u64_as_f2(acc[rp][j]);
#pragma unroll
        for (int h = 0; h < 2; h++) {
            int gr = gre + h;
            if (gr >= M) break;
            float4 v0, v1;
            if (h == 0) {
                v0 = make_float4(p[0].x, p[1].x, p[2].x, p[3].x);
                v1 = make_float4(p[4].x, p[5].x, p[6].x, p[7].x);
            } else {
                v0 = make_float4(p[0].y, p[1].y, p[2].y, p[3].y);
                v1 = make_float4(p[4].y, p[5].y, p[6].y, p[7].y);
            }
            *reinterpret_cast<float4*>(&g_hs1[(size_t)gr * 128 + c0]) = v0;
            *reinterpret_cast<float4*>(&g_hs1[(size_t)gr * 128 + c0 + 4]) = v1;
        }
    }
}

// ---------------------------------------------------------------------------
// Edge aggregate 1: agg1[d] = dinv[d]*hs1[d] + sum dinv[s]*hs1[s].
// 256 threads = 8 warps; warp pair (2q, 2q+1) shares bucket blk*4+q, each
// warp owns one 64-float feature half (float2 per lane). No sync needed:
// disjoint smem columns. Per-feature accumulation order identical to R10.
// ---------------------------------------------------------------------------
__global__ __launch_bounds__(256) void k_edge1(int n, int nb) {
    __shared__ __align__(16) float acc[4][16][128];

    const int w = threadIdx.x >> 5;
    const int bq = w >> 1;
    const int b = blockIdx.x * 4 + bq;
    if (b >= nb) return;
    const int lane = threadIdx.x & 31;
    const int f2 = (w & 1) * 64 + lane * 2;  // float offset in row
    const int n0 = b * 16;

#pragma unroll
    for (int r = 0; r < 16; r++) {
        int node = n0 + r;
        float2 v = make_float2(0.f, 0.f);
        if (node < n) {
            v = *reinterpret_cast<const float2*>(&g_hs1[(size_t)node * 128 + f2]);
            float dv = g_dinv[node];
            v.x *= dv;
            v.y *= dv;
        }
        *reinterpret_cast<float2*>(&acc[bq][r][f2]) = v;
    }

    int e = g_bstart[b];
    const int e1 = g_bstart[b + 1];
    for (; e + 7 < e1; e += 8) {
        int ss[8], dd[8];
#pragma unroll
        for (int j = 0; j < 8; j++) {
            ss[j] = g_esrc[e + j];
            dd[j] = g_edst[e + j];
        }
        float2 vv[8];
        float dv[8];
#pragma unroll
        for (int j = 0; j < 8; j++) {
            vv[j] = *reinterpret_cast<const float2*>(&g_hs1[(size_t)ss[j] * 128 + f2]);
            dv[j] = g_dinv[ss[j]];
        }
#pragma unroll
        for (int j = 0; j < 8; j++) {
            float2* a = reinterpret_cast<float2*>(&acc[bq][dd[j] - n0][f2]);
            float2 o = *a;
            o.x = fmaf(dv[j], vv[j].x, o.x);
            o.y = fmaf(dv[j], vv[j].y, o.y);
            *a = o;
        }
    }
    for (; e < e1; e++) {
        int s = g_esrc[e], d = g_edst[e];
        float2 v = *reinterpret_cast<const float2*>(&g_hs1[(size_t)s * 128 + f2]);
        float dv = g_dinv[s];
        float2* a = reinterpret_cast<float2*>(&acc[bq][d - n0][f2]);
        float2 o = *a;
        o.x = fmaf(dv, v.x, o.x);
        o.y = fmaf(dv, v.y, o.y);
        *a = o;
    }

#pragma unroll
    for (int r = 0; r < 16; r++) {
        int node = n0 + r;
        if (node < n)
            *reinterpret_cast<float2*>(&g_agg1[(size_t)node * 128 + f2]) =
                *reinterpret_cast<const float2*>(&acc[bq][r][f2]);
    }
}

// ---------------------------------------------------------------------------
// GEMM2 (fp32, R10 version): A[r][k] = relu(dinv[r]*agg1[r][k] + b1[k]) fused
// on load; hs2 = dinv[r]*(A @ W2). Block 64x64, thread tile 4x4.
// ---------------------------------------------------------------------------
__global__ __launch_bounds__(256) void k_gemm2(const float* __restrict__ W2,
                                               const float* __restrict__ B1,
                                               int M) {
    __shared__ float As[64][33];
    __shared__ float Bs[32][64];

    const int tid = threadIdx.x;
    const int row0 = blockIdx.x * 64;
    const int tx = tid & 15, ty = tid >> 4;
    const int r0 = ty * 4, c0 = tx * 4;

    float acc[4][4];
#pragma unroll
    for (int i = 0; i < 4; i++)
#pragma unroll
        for (int j = 0; j < 4; j++) acc[i][j] = 0.f;

    for (int kc = 0; kc < 4; kc++) {
#pragma unroll
        for (int l = 0; l < 2; l++) {
            int i = tid + l * 256;
            int r = i >> 3, q = i & 7;
            int gr = row0 + r;
            float4 v = make_float4(0.f, 0.f, 0.f, 0.f);
            if (gr < M) {
                v = reinterpret_cast<const float4*>(g_agg1)[(size_t)gr * 32 + kc * 8 + q];
                float dv = g_dinv[gr];
                int kb = kc * 32 + q * 4;
                v.x = fmaxf(fmaf(dv, v.x, B1[kb + 0]), 0.f);
                v.y = fmaxf(fmaf(dv, v.y, B1[kb + 1]), 0.f);
                v.z = fmaxf(fmaf(dv, v.z, B1[kb + 2]), 0.f);
                v.w = fmaxf(fmaf(dv, v.w, B1[kb + 3]), 0.f);
            }
            As[r][q * 4 + 0] = v.x;
            As[r][q * 4 + 1] = v.y;
            As[r][q * 4 + 2] = v.z;
            As[r][q * 4 + 3] = v.w;
        }
#pragma unroll
        for (int l = 0; l < 2; l++) {
            int i = tid + l * 256;
            reinterpret_cast<float4*>(&Bs[0][0])[i] =
                reinterpret_cast<const float4*>(W2 + (size_t)kc * 32 * 64)[i];
        }
        __syncthreads();

#pragma unroll
        for (int k = 0; k < 32; k++) {
            float a[4];
#pragma unroll
            for (int i = 0; i < 4; i++) a[i] = As[r0 + i][k];
            float4 b4 = *reinterpret_cast<float4*>(&Bs[k][c0]);
            float b[4] = {b4.x, b4.y, b4.z, b4.w};
#pragma unroll
            for (int i = 0; i < 4; i++)
#pragma unroll
                for (int j = 0; j < 4; j++) acc[i][j] = fmaf(a[i], b[j], acc[i][j]);
        }
        __syncthreads();
    }

#pragma unroll
    for (int i = 0; i < 4; i++) {
        int gr = row0 + r0 + i;
        if (gr >= M) break;
        float dv = g_dinv[gr];
        float4 v;
        v.x = acc[i][0] * dv;
        v.y = acc[i][1] * dv;
        v.z = acc[i][2] * dv;
        v.w = acc[i][3] * dv;
        *reinterpret_cast<float4*>(&g_hs2[(size_t)gr * 64 + c0]) = v;
    }
}

// ---------------------------------------------------------------------------
// Edge aggregate 2 + final: OUT[d] = dinv[d]*(hs2[d]+sum hs2[src]) + b2.
// 256 threads = 8 warps; warp pair per bucket, one 32-float half per warp
// (scalar float per lane). Per-feature accumulation order identical to R10.
// ---------------------------------------------------------------------------
__global__ __launch_bounds__(256) void k_edge2(float* __restrict__ OUT,
                                               const float* __restrict__ B2,
                                               int n, int nb) {
    __shared__ float acc[4][16][64];

    const int w = threadIdx.x >> 5;
    const int bq = w >> 1;
    const int b = blockIdx.x * 4 + bq;
    if (b >= nb) return;
    const int lane = threadIdx.x & 31;
    const int f1 = (w & 1) * 32 + lane;  // float offset in row
    const int n0 = b * 16;

#pragma unroll
    for (int r = 0; r < 16; r++) {
        int node = n0 + r;
        float v = 0.f;
        if (node < n) v = g_hs2[(size_t)node * 64 + f1];
        acc[bq][r][f1] = v;
    }

    int e = g_bstart[b];
    const int e1 = g_bstart[b + 1];
    for (; e + 7 < e1; e += 8) {
        int ss[8], dd[8];
#pragma unroll
        for (int j = 0; j < 8; j++) {
            ss[j] = g_esrc[e + j];
            dd[j] = g_edst[e + j];
        }
        float vv[8];
#pragma unroll
        for (int j = 0; j < 8; j++)
            vv[j] = g_hs2[(size_t)ss[j] * 64 + f1];
#pragma unroll
        for (int j = 0; j < 8; j++)
            acc[bq][dd[j] - n0][f1] += vv[j];
    }
    for (; e < e1; e++) {
        int s = g_esrc[e], d = g_edst[e];
        acc[bq][d - n0][f1] += g_hs2[(size_t)s * 64 + f1];
    }

    const float bb = B2[f1];
#pragma unroll
    for (int r = 0; r < 16; r++) {
        int node = n0 + r;
        if (node < n) {
            float dv = g_dinv[node];
            OUT[(size_t)node * 64 + f1] = fmaf(dv, acc[bq][r][f1], bb);
        }
    }
}

// ---------------------------------------------------------------------------
extern "C" void kernel_launch(void* const* d_in, const int* in_sizes, int n_in,
                              void* d_out, int out_size) {
    const float* x  = (const float*)d_in[0];
    const int*   ei = (const int*)d_in[1];
    const float* W1 = (const float*)d_in[2];
    const float* b1 = (const float*)d_in[3];
    const float* W2 = (const float*)d_in[4];
    const float* b2 = (const float*)d_in[5];
    float* out = (float*)d_out;

    const int N = in_sizes[0] / 128;
    const int E = in_sizes[1] / 2;
    const int NB = (N + 15) / 16;
    const int* src = ei;
    const int* dst = ei + E;

    static cudaStream_t side = nullptr;
    static cudaEvent_t evA = nullptr, evB = nullptr;
    if (!side) {
        cudaStreamCreateWithFlags(&side, cudaStreamNonBlocking);
        cudaEventCreateWithFlags(&evA, cudaEventDisableTiming);
        cudaEventCreateWithFlags(&evB, cudaEventDisableTiming);
    }

    // Fork: preprocessing on side stream, GEMM1 (independent) on main stream.
    cudaEventRecord(evA, 0);
    cudaStreamWaitEvent(side, evA, 0);

    int mx = (N > NB) ? N : NB;
    k_init<<<(mx + 255) / 256, 256, 0, side>>>(N, NB);
    k_count<<<(E + 255) / 256, 256, 0, side>>>(dst, E);
    k_dinv<<<(N + 255) / 256, 256, 0, side>>>(N);
    k_scan<<<1, 1024, 0, side>>>(NB);
    k_sort<<<(E + 255) / 256, 256, 0, side>>>(src, dst, E);
    cudaEventRecord(evB, side);

    k_gemm1<<<(N + 127) / 128, 256>>>(x, W1, N);

    // Join: edge1 needs both GEMM1 output and sorted edges + dinv.
    cudaStreamWaitEvent(0, evB, 0);

    k_edge1<<<(NB + 3) / 4, 256>>>(N, NB);
    k_gemm2<<<(N + 63) / 64, 256>>>(W2, b1, N);
    k_edge2<<<(NB + 3) / 4, 256>>>(out, b2, N, NB);
}

// round 15
// speedup vs baseline: 1.6388x; 1.6388x over previous
#include <cuda_runtime.h>
#include <cuda_fp16.h>
#include <cstdint>

// ---------------------------------------------------------------------------
// StandGCN2: 2-layer GCN. N<=100096, F=128 -> 128 -> 64.
//   dinv = rsqrt(1+indeg)
//   hs1  = x @ W1                      (GEMM1 f32x2; output stored as fp16)
//   agg1[d] = dinv[d]*hs1[d] + sum dinv[s]*hs1[s]   (bucketed smem scatter,
//                                       fp32 accumulation, fp16 gathers)
//   h1   = relu(dinv*agg1 + b1)        (fused into GEMM2 A-load)
//   hs2  = dinv[r]*(h1 @ W2)           (GEMM2 fp32; output stored as fp16)
//   OUT[d] = dinv[d]*(hs2[d]+sum hs2[src]) + b2
// R10 structure exactly (best: 267.3us); ONLY change: hs1/hs2 are fp16 to
// halve bytes-per-edge in the gather loops.
// ---------------------------------------------------------------------------

#define MAXN 100096
#define MAXB (MAXN / 16)
#define MAXE 1200000

__device__ float g_deg[MAXN];
__device__ float g_dinv[MAXN];
__device__ __align__(16) __half g_hs1[(size_t)MAXN * 128];
__device__ __align__(16) float g_agg1[(size_t)MAXN * 128];
__device__ __align__(16) __half g_hs2[(size_t)MAXN * 64];

__device__ int g_esrc[MAXE];
__device__ int g_edst[MAXE];
__device__ int g_bstart[MAXB + 1];
__device__ int g_bcur[MAXB];

typedef unsigned long long u64;

#define FMA2(d, a, b) \
    asm("fma.rn.f32x2 %0, %1, %2, %3;" : "=l"(d) : "l"(a), "l"(b), "l"(d))
#define DUP2(d, x) \
    asm("mov.b64 %0, {%1, %1};" : "=l"(d) : "r"(__float_as_uint(x)))

__device__ __forceinline__ float2 u64_as_f2(u64 v) {
    float2 r;
    asm("mov.b64 {%0, %1}, %2;" : "=f"(r.x), "=f"(r.y) : "l"(v));
    return r;
}

// ---------------------------------------------------------------------------
// Preprocessing (side stream)
// ---------------------------------------------------------------------------
__global__ void k_init(int n, int nb) {
    int i = blockIdx.x * blockDim.x + threadIdx.x;
    if (i < n) g_deg[i] = 1.0f;
    if (i < nb) g_bcur[i] = 0;
}

__global__ void k_count(const int* __restrict__ dst, int e) {
    int i = blockIdx.x * blockDim.x + threadIdx.x;
    if (i >= e) return;
    int d = dst[i];
    atomicAdd(&g_deg[d], 1.0f);
    atomicAdd(&g_bcur[d >> 4], 1);
}

__global__ void k_dinv(int n) {
    int i = blockIdx.x * blockDim.x + threadIdx.x;
    if (i < n) g_dinv[i] = rsqrtf(g_deg[i]);
}

// Single-block warp-shuffle exclusive scan over <=8192 bucket counts.
__global__ void k_scan(int nb) {
    __shared__ int wsum[32];
    const int t = threadIdx.x;
    const int per = (nb + 1023) / 1024;  // <= 8
    const int base = t * per;
    int v[8];
    int s = 0;
#pragma unroll
    for (int i = 0; i < 8; i++) {
        int idx = base + i;
        int x = (i < per && idx < nb) ? g_bcur[idx] : 0;
        v[i] = s;
        s += x;
    }
    const int lane = t & 31, w = t >> 5;
    int ps = s;
#pragma unroll
    for (int o = 1; o < 32; o <<= 1) {
        int y = __shfl_up_sync(0xFFFFFFFFu, ps, o);
        if (lane >= o) ps += y;
    }
    if (lane == 31) wsum[w] = ps;
    __syncthreads();
    if (w == 0) {
        int ws = wsum[lane];
#pragma unroll
        for (int o = 1; o < 32; o <<= 1) {
            int y = __shfl_up_sync(0xFFFFFFFFu, ws, o);
            if (lane >= o) ws += y;
        }
        wsum[lane] = ws;
    }
    __syncthreads();
    int excl = ps - s + (w > 0 ? wsum[w - 1] : 0);
#pragma unroll
    for (int i = 0; i < 8; i++) {
        int idx = base + i;
        if (i < per && idx < nb) {
            int e = excl + v[i];
            g_bstart[idx] = e;
            g_bcur[idx] = e;
        }
    }
    if (t == 1023) g_bstart[nb] = excl + s;
}

__global__ void k_sort(const int* __restrict__ src, const int* __restrict__ dst,
                       int e) {
    int i = blockIdx.x * blockDim.x + threadIdx.x;
    if (i >= e) return;
    int s = src[i], d = dst[i];
    int pos = atomicAdd(&g_bcur[d >> 4], 1);
    g_esrc[pos] = s;
    g_edst[pos] = d;
}

// ---------------------------------------------------------------------------
// GEMM1: hs1 = X @ W1 (raw, stored fp16),  X:[M,128], W1:[128,128]
// Block 128x128, 256 threads, 8x8 microtile via f32x2, double-buffered.
// ---------------------------------------------------------------------------
__global__ __launch_bounds__(256, 2) void k_gemm1(const float* __restrict__ X,
                                                  const float* __restrict__ W,
                                                  int M) {
    __shared__ float As[2][16][128];
    __shared__ float Bs[2][16][128];

    const int tid = threadIdx.x;
    const int row0 = blockIdx.x * 128;
    const int tx = tid & 15, ty = tid >> 4;
    const int r0 = ty * 8, c0 = tx * 8;

    u64 acc[4][8];
#pragma unroll
    for (int i = 0; i < 4; i++)
#pragma unroll
        for (int j = 0; j < 8; j++) acc[i][j] = 0ull;

    float4 ra[2], rb[2];

    auto ldg = [&](int kc) {
#pragma unroll
        for (int l = 0; l < 2; l++) {
            int i = tid + l * 256;
            int r = i & 127, q4 = i >> 7;
            int gr = row0 + r;
            ra[l] = make_float4(0.f, 0.f, 0.f, 0.f);
            if (gr < M)
                ra[l] = reinterpret_cast<const float4*>(X)[(size_t)gr * 32 + kc * 4 + q4];
            rb[l] = reinterpret_cast<const float4*>(W)[(size_t)kc * 512 + i];
        }
    };
    auto sts = [&](int buf) {
#pragma unroll
        for (int l = 0; l < 2; l++) {
            int i = tid + l * 256;
            int r = i & 127, q4 = i >> 7;
            As[buf][q4 * 4 + 0][r] = ra[l].x;
            As[buf][q4 * 4 + 1][r] = ra[l].y;
            As[buf][q4 * 4 + 2][r] = ra[l].z;
            As[buf][q4 * 4 + 3][r] = ra[l].w;
            reinterpret_cast<float4*>(&Bs[buf][0][0])[i] = rb[l];
        }
    };

    ldg(0);
    sts(0);
    ldg(1);
    __syncthreads();

    for (int kc = 0; kc < 8; kc++) {
        const int cur = kc & 1;
        if (kc + 1 < 8) sts((kc + 1) & 1);
        if (kc + 2 < 8) ldg(kc + 2);
#pragma unroll
        for (int k = 0; k < 16; k++) {
            ulonglong2 a01 = *reinterpret_cast<const ulonglong2*>(&As[cur][k][r0]);
            ulonglong2 a23 = *reinterpret_cast<const ulonglong2*>(&As[cur][k][r0 + 4]);
            float4 bl = *reinterpret_cast<const float4*>(&Bs[cur][k][c0]);
            float4 bh = *reinterpret_cast<const float4*>(&Bs[cur][k][c0 + 4]);
            u64 ap[4] = {a01.x, a01.y, a23.x, a23.y};
            u64 bb[8];
            DUP2(bb[0], bl.x); DUP2(bb[1], bl.y); DUP2(bb[2], bl.z); DUP2(bb[3], bl.w);
            DUP2(bb[4], bh.x); DUP2(bb[5], bh.y); DUP2(bb[6], bh.z); DUP2(bb[7], bh.w);
#pragma unroll
            for (int rp = 0; rp < 4; rp++)
#pragma unroll
                for (int j = 0; j < 8; j++) FMA2(acc[rp][j], ap[rp], bb[j]);
        }
        __syncthreads();
    }

#pragma unroll
    for (int rp = 0; rp < 4; rp++) {
        int gre = row0 + r0 + 2 * rp;
        float2 p[8];
#pragma unroll
        for (int j = 0; j < 8; j++) p[j] = u64_as_f2(acc[rp][j]);
#pragma unroll
        for (int h = 0; h < 2; h++) {
            int gr = gre + h;
            if (gr >= M) break;
            float4 v0, v1;
            if (h == 0) {
                v0 = make_float4(p[0].x, p[1].x, p[2].x, p[3].x);
                v1 = make_float4(p[4].x, p[5].x, p[6].x, p[7].x);
            } else {
                v0 = make_float4(p[0].y, p[1].y, p[2].y, p[3].y);
                v1 = make_float4(p[4].y, p[5].y, p[6].y, p[7].y);
            }
            __half2 hh[4];
            hh[0] = __floats2half2_rn(v0.x, v0.y);
            hh[1] = __floats2half2_rn(v0.z, v0.w);
            hh[2] = __floats2half2_rn(v1.x, v1.y);
            hh[3] = __floats2half2_rn(v1.z, v1.w);
            *reinterpret_cast<uint4*>(&g_hs1[(size_t)gr * 128 + c0]) =
                *reinterpret_cast<const uint4*>(hh);
        }
    }
}

// ---------------------------------------------------------------------------
// Edge aggregate 1: agg1[d] = dinv[d]*hs1[d] + sum dinv[s]*hs1[s].
// Warp per 16-node bucket, 8-wide unrolled gather (R10 structure).
// fp16 gathers (8B/lane), fp32 accumulation.
// ---------------------------------------------------------------------------
__global__ __launch_bounds__(128) void k_edge1(int n, int nb) {
    __shared__ __align__(16) float acc[4][16][128];

    const int w = threadIdx.x >> 5;
    const int l4 = (threadIdx.x & 31) * 4;
    const int b = blockIdx.x * 4 + w;
    if (b >= nb) return;
    const int n0 = b * 16;

#pragma unroll
    for (int r = 0; r < 16; r++) {
        int node = n0 + r;
        float4 v = make_float4(0.f, 0.f, 0.f, 0.f);
        if (node < n) {
            uint2 u = *reinterpret_cast<const uint2*>(&g_hs1[(size_t)node * 128 + l4]);
            float2 f0 = __half22float2(*reinterpret_cast<const __half2*>(&u.x));
            float2 f1 = __half22float2(*reinterpret_cast<const __half2*>(&u.y));
            float dv = g_dinv[node];
            v = make_float4(f0.x * dv, f0.y * dv, f1.x * dv, f1.y * dv);
        }
        *reinterpret_cast<float4*>(&acc[w][r][l4]) = v;
    }

    int e = g_bstart[b];
    const int e1 = g_bstart[b + 1];
    for (; e + 7 < e1; e += 8) {
        int ss[8], dd[8];
#pragma unroll
        for (int j = 0; j < 8; j++) {
            ss[j] = g_esrc[e + j];
            dd[j] = g_edst[e + j];
        }
        uint2 uu[8];
        float dv[8];
#pragma unroll
        for (int j = 0; j < 8; j++) {
            uu[j] = *reinterpret_cast<const uint2*>(&g_hs1[(size_t)ss[j] * 128 + l4]);
            dv[j] = g_dinv[ss[j]];
        }
#pragma unroll
        for (int j = 0; j < 8; j++) {
            float2 f0 = __half22float2(*reinterpret_cast<const __half2*>(&uu[j].x));
            float2 f1 = __half22float2(*reinterpret_cast<const __half2*>(&uu[j].y));
            float4* a = reinterpret_cast<float4*>(&acc[w][dd[j] - n0][l4]);
            float4 o = *a;
            o.x = fmaf(dv[j], f0.x, o.x);
            o.y = fmaf(dv[j], f0.y, o.y);
            o.z = fmaf(dv[j], f1.x, o.z);
            o.w = fmaf(dv[j], f1.y, o.w);
            *a = o;
        }
    }
    for (; e < e1; e++) {
        int s = g_esrc[e], d = g_edst[e];
        uint2 u = *reinterpret_cast<const uint2*>(&g_hs1[(size_t)s * 128 + l4]);
        float2 f0 = __half22float2(*reinterpret_cast<const __half2*>(&u.x));
        float2 f1 = __half22float2(*reinterpret_cast<const __half2*>(&u.y));
        float dv = g_dinv[s];
        float4* a = reinterpret_cast<float4*>(&acc[w][d - n0][l4]);
        float4 o = *a;
        o.x = fmaf(dv, f0.x, o.x);
        o.y = fmaf(dv, f0.y, o.y);
        o.z = fmaf(dv, f1.x, o.z);
        o.w = fmaf(dv, f1.y, o.w);
        *a = o;
    }

#pragma unroll
    for (int r = 0; r < 16; r++) {
        int node = n0 + r;
        if (node < n)
            *reinterpret_cast<float4*>(&g_agg1[(size_t)node * 128 + l4]) =
                *reinterpret_cast<const float4*>(&acc[w][r][l4]);
    }
}

// ---------------------------------------------------------------------------
// GEMM2 (fp32, R10 version): A[r][k] = relu(dinv[r]*agg1[r][k] + b1[k]) fused
// on load; hs2 = dinv[r]*(A @ W2), stored fp16. Block 64x64, thread tile 4x4.
// ---------------------------------------------------------------------------
__global__ __launch_bounds__(256) void k_gemm2(const float* __restrict__ W2,
                                               const float* __restrict__ B1,
                                               int M) {
    __shared__ float As[64][33];
    __shared__ float Bs[32][64];

    const int tid = threadIdx.x;
    const int row0 = blockIdx.x * 64;
    const int tx = tid & 15, ty = tid >> 4;
    const int r0 = ty * 4, c0 = tx * 4;

    float acc[4][4];
#pragma unroll
    for (int i = 0; i < 4; i++)
#pragma unroll
        for (int j = 0; j < 4; j++) acc[i][j] = 0.f;

    for (int kc = 0; kc < 4; kc++) {
#pragma unroll
        for (int l = 0; l < 2; l++) {
            int i = tid + l * 256;
            int r = i >> 3, q = i & 7;
            int gr = row0 + r;
            float4 v = make_float4(0.f, 0.f, 0.f, 0.f);
            if (gr < M) {
                v = reinterpret_cast<const float4*>(g_agg1)[(size_t)gr * 32 + kc * 8 + q];
                float dv = g_dinv[gr];
                int kb = kc * 32 + q * 4;
                v.x = fmaxf(fmaf(dv, v.x, B1[kb + 0]), 0.f);
                v.y = fmaxf(fmaf(dv, v.y, B1[kb + 1]), 0.f);
                v.z = fmaxf(fmaf(dv, v.z, B1[kb + 2]), 0.f);
                v.w = fmaxf(fmaf(dv, v.w, B1[kb + 3]), 0.f);
            }
            As[r][q * 4 + 0] = v.x;
            As[r][q * 4 + 1] = v.y;
            As[r][q * 4 + 2] = v.z;
            As[r][q * 4 + 3] = v.w;
        }
#pragma unroll
        for (int l = 0; l < 2; l++) {
            int i = tid + l * 256;
            reinterpret_cast<float4*>(&Bs[0][0])[i] =
                reinterpret_cast<const float4*>(W2 + (size_t)kc * 32 * 64)[i];
        }
        __syncthreads();

#pragma unroll
        for (int k = 0; k < 32; k++) {
            float a[4];
#pragma unroll
            for (int i = 0; i < 4; i++) a[i] = As[r0 + i][k];
            float4 b4 = *reinterpret_cast<float4*>(&Bs[k][c0]);
            float b[4] = {b4.x, b4.y, b4.z, b4.w};
#pragma unroll
            for (int i = 0; i < 4; i++)
#pragma unroll
                for (int j = 0; j < 4; j++) acc[i][j] = fmaf(a[i], b[j], acc[i][j]);
        }
        __syncthreads();
    }

#pragma unroll
    for (int i = 0; i < 4; i++) {
        int gr = row0 + r0 + i;
        if (gr >= M) break;
        float dv = g_dinv[gr];
        __half2 hh[2];
        hh[0] = __floats2half2_rn(acc[i][0] * dv, acc[i][1] * dv);
        hh[1] = __floats2half2_rn(acc[i][2] * dv, acc[i][3] * dv);
        *reinterpret_cast<uint2*>(&g_hs2[(size_t)gr * 64 + c0]) =
            *reinterpret_cast<const uint2*>(hh);
    }
}

// ---------------------------------------------------------------------------
// Edge aggregate 2 + final: OUT[d] = dinv[d]*(hs2[d]+sum hs2[src]) + b2.
// Warp per 16-node bucket, 8-wide unrolled gather (R10 structure).
// fp16 gathers (4B/lane), fp32 accumulation.
// ---------------------------------------------------------------------------
__global__ __launch_bounds__(128) void k_edge2(float* __restrict__ OUT,
                                               const float* __restrict__ B2,
                                               int n, int nb) {
    __shared__ __align__(8) float acc[4][16][64];

    const int w = threadIdx.x >> 5;
    const int l2 = (threadIdx.x & 31) * 2;
    const int b = blockIdx.x * 4 + w;
    if (b >= nb) return;
    const int n0 = b * 16;

#pragma unroll
    for (int r = 0; r < 16; r++) {
        int node = n0 + r;
        float2 v = make_float2(0.f, 0.f);
        if (node < n)
            v = __half22float2(
                *reinterpret_cast<const __half2*>(&g_hs2[(size_t)node * 64 + l2]));
        *reinterpret_cast<float2*>(&acc[w][r][l2]) = v;
    }

    int e = g_bstart[b];
    const int e1 = g_bstart[b + 1];
    for (; e + 7 < e1; e += 8) {
        int ss[8], dd[8];
#pragma unroll
        for (int j = 0; j < 8; j++) {
            ss[j] = g_esrc[e + j];
            dd[j] = g_edst[e + j];
        }
        uint32_t uu[8];
#pragma unroll
        for (int j = 0; j < 8; j++)
            uu[j] = *reinterpret_cast<const uint32_t*>(&g_hs2[(size_t)ss[j] * 64 + l2]);
#pragma unroll
        for (int j = 0; j < 8; j++) {
            float2 f = __half22float2(*reinterpret_cast<const __half2*>(&uu[j]));
            float2* a = reinterpret_cast<float2*>(&acc[w][dd[j] - n0][l2]);
            float2 o = *a;
            o.x += f.x;
            o.y += f.y;
            *a = o;
        }
    }
    for (; e < e1; e++) {
        int s = g_esrc[e], d = g_edst[e];
        float2 f = __half22float2(
            *reinterpret_cast<const __half2*>(&g_hs2[(size_t)s * 64 + l2]));
        float2* a = reinterpret_cast<float2*>(&acc[w][d - n0][l2]);
        float2 o = *a;
        o.x += f.x;
        o.y += f.y;
        *a = o;
    }

    float2 bb = *reinterpret_cast<const float2*>(&B2[l2]);
#pragma unroll
    for (int r = 0; r < 16; r++) {
        int node = n0 + r;
        if (node < n) {
            float dv = g_dinv[node];
            float2 o = *reinterpret_cast<const float2*>(&acc[w][r][l2]);
            o.x = fmaf(dv, o.x, bb.x);
            o.y = fmaf(dv, o.y, bb.y);
            *reinterpret_cast<float2*>(&OUT[(size_t)node * 64 + l2]) = o;
        }
    }
}

// ---------------------------------------------------------------------------
extern "C" void kernel_launch(void* const* d_in, const int* in_sizes, int n_in,
                              void* d_out, int out_size) {
    const float* x  = (const float*)d_in[0];
    const int*   ei = (const int*)d_in[1];
    const float* W1 = (const float*)d_in[2];
    const float* b1 = (const float*)d_in[3];
    const float* W2 = (const float*)d_in[4];
    const float* b2 = (const float*)d_in[5];
    float* out = (float*)d_out;

    const int N = in_sizes[0] / 128;
    const int E = in_sizes[1] / 2;
    const int NB = (N + 15) / 16;
    const int* src = ei;
    const int* dst = ei + E;

    static cudaStream_t side = nullptr;
    static cudaEvent_t evA = nullptr, evB = nullptr;
    if (!side) {
        cudaStreamCreateWithFlags(&side, cudaStreamNonBlocking);
        cudaEventCreateWithFlags(&evA, cudaEventDisableTiming);
        cudaEventCreateWithFlags(&evB, cudaEventDisableTiming);
    }

    // Fork: preprocessing on side stream, GEMM1 (independent) on main stream.
    cudaEventRecord(evA, 0);
    cudaStreamWaitEvent(side, evA, 0);

    int mx = (N > NB) ? N : NB;
    k_init<<<(mx + 255) / 256, 256, 0, side>>>(N, NB);
    k_count<<<(E + 255) / 256, 256, 0, side>>>(dst, E);
    k_dinv<<<(N + 255) / 256, 256, 0, side>>>(N);
    k_scan<<<1, 1024, 0, side>>>(NB);
    k_sort<<<(E + 255) / 256, 256, 0, side>>>(src, dst, E);
    cudaEventRecord(evB, side);

    k_gemm1<<<(N + 127) / 128, 256>>>(x, W1, N);

    // Join: edge1 needs both GEMM1 output and sorted edges + dinv.
    cudaStreamWaitEvent(0, evB, 0);

    k_edge1<<<(NB + 3) / 4, 128>>>(N, NB);
    k_gemm2<<<(N + 63) / 64, 256>>>(W2, b1, N);
    k_edge2<<<(NB + 3) / 4, 128>>>(out, b2, N, NB);
}

// round 17
// speedup vs baseline: 1.7748x; 1.0830x over previous
#include <cuda_runtime.h>
#include <cuda_fp16.h>
#include <cstdint>

// ---------------------------------------------------------------------------
// StandGCN2: 2-layer GCN. N<=100096, F=128 -> 128 -> 64.
//   dinv = rsqrt(1+indeg)
//   hs1  = x @ W1                      (GEMM1 f32x2; stored fp16)
//   h1[d] = relu(dinv[d]*(dinv[d]*hs1[d] + sum dinv[s]*hs1[s]) + b1)
//           (bucketed smem scatter; activation in epilogue; stored fp16)
//   hs2  = dinv[r]*(h1 @ W2)           (GEMM2 fp32 compute, fp16 A-loads;
//                                       stored fp16)
//   OUT[d] = dinv[d]*(hs2[d]+sum hs2[src]) + b2
// vs R15 (251.0us): edges packed into ONE int/edge ((doff<<17)|src), and the
// layer-1 activation moved into edge1's epilogue with fp16 h1 storage
// (halves edge1 stores + GEMM2 A traffic).
// (Resubmission of R16 -- previous run died to a container infra failure.)
// ---------------------------------------------------------------------------

#define MAXN 100096
#define MAXB (MAXN / 16)
#define MAXE 1200000

__device__ float g_deg[MAXN];
__device__ float g_dinv[MAXN];
__device__ __align__(16) __half g_hs1[(size_t)MAXN * 128];
__device__ __align__(16) __half g_h1[(size_t)MAXN * 128];   // relu'd layer-1
__device__ __align__(16) __half g_hs2[(size_t)MAXN * 64];

__device__ int g_epack[MAXE];       // (d & 15) << 17 | src
__device__ int g_bstart[MAXB + 1];
__device__ int g_bcur[MAXB];

typedef unsigned long long u64;

#define FMA2(d, a, b) \
    asm("fma.rn.f32x2 %0, %1, %2, %3;" : "=l"(d) : "l"(a), "l"(b), "l"(d))
#define DUP2(d, x) \
    asm("mov.b64 %0, {%1, %1};" : "=l"(d) : "r"(__float_as_uint(x)))

__device__ __forceinline__ float2 u64_as_f2(u64 v) {
    float2 r;
    asm("mov.b64 {%0, %1}, %2;" : "=f"(r.x), "=f"(r.y) : "l"(v));
    return r;
}

// ---------------------------------------------------------------------------
// Preprocessing (side stream)
// ---------------------------------------------------------------------------
__global__ void k_init(int n, int nb) {
    int i = blockIdx.x * blockDim.x + threadIdx.x;
    if (i < n) g_deg[i] = 1.0f;
    if (i < nb) g_bcur[i] = 0;
}

__global__ void k_count(const int* __restrict__ dst, int e) {
    int i = blockIdx.x * blockDim.x + threadIdx.x;
    if (i >= e) return;
    int d = dst[i];
    atomicAdd(&g_deg[d], 1.0f);
    atomicAdd(&g_bcur[d >> 4], 1);
}

__global__ void k_dinv(int n) {
    int i = blockIdx.x * blockDim.x + threadIdx.x;
    if (i < n) g_dinv[i] = rsqrtf(g_deg[i]);
}

// Single-block warp-shuffle exclusive scan over <=8192 bucket counts.
__global__ void k_scan(int nb) {
    __shared__ int wsum[32];
    const int t = threadIdx.x;
    const int per = (nb + 1023) / 1024;  // <= 8
    const int base = t * per;
    int v[8];
    int s = 0;
#pragma unroll
    for (int i = 0; i < 8; i++) {
        int idx = base + i;
        int x = (i < per && idx < nb) ? g_bcur[idx] : 0;
        v[i] = s;
        s += x;
    }
    const int lane = t & 31, w = t >> 5;
    int ps = s;
#pragma unroll
    for (int o = 1; o < 32; o <<= 1) {
        int y = __shfl_up_sync(0xFFFFFFFFu, ps, o);
        if (lane >= o) ps += y;
    }
    if (lane == 31) wsum[w] = ps;
    __syncthreads();
    if (w == 0) {
        int ws = wsum[lane];
#pragma unroll
        for (int o = 1; o < 32; o <<= 1) {
            int y = __shfl_up_sync(0xFFFFFFFFu, ws, o);
            if (lane >= o) ws += y;
        }
        wsum[lane] = ws;
    }
    __syncthreads();
    int excl = ps - s + (w > 0 ? wsum[w - 1] : 0);
#pragma unroll
    for (int i = 0; i < 8; i++) {
        int idx = base + i;
        if (i < per && idx < nb) {
            int e = excl + v[i];
            g_bstart[idx] = e;
            g_bcur[idx] = e;
        }
    }
    if (t == 1023) g_bstart[nb] = excl + s;
}

__global__ void k_sort(const int* __restrict__ src, const int* __restrict__ dst,
                       int e) {
    int i = blockIdx.x * blockDim.x + threadIdx.x;
    if (i >= e) return;
    int s = src[i], d = dst[i];
    int pos = atomicAdd(&g_bcur[d >> 4], 1);
    g_epack[pos] = ((d & 15) << 17) | s;
}

// ---------------------------------------------------------------------------
// GEMM1: hs1 = X @ W1 (raw, stored fp16),  X:[M,128], W1:[128,128]
// Block 128x128, 256 threads, 8x8 microtile via f32x2, double-buffered.
// ---------------------------------------------------------------------------
__global__ __launch_bounds__(256, 2) void k_gemm1(const float* __restrict__ X,
                                                  const float* __restrict__ W,
                                                  int M) {
    __shared__ float As[2][16][128];
    __shared__ float Bs[2][16][128];

    const int tid = threadIdx.x;
    const int row0 = blockIdx.x * 128;
    const int tx = tid & 15, ty = tid >> 4;
    const int r0 = ty * 8, c0 = tx * 8;

    u64 acc[4][8];
#pragma unroll
    for (int i = 0; i < 4; i++)
#pragma unroll
        for (int j = 0; j < 8; j++) acc[i][j] = 0ull;

    float4 ra[2], rb[2];

    auto ldg = [&](int kc) {
#pragma unroll
        for (int l = 0; l < 2; l++) {
            int i = tid + l * 256;
            int r = i & 127, q4 = i >> 7;
            int gr = row0 + r;
            ra[l] = make_float4(0.f, 0.f, 0.f, 0.f);
            if (gr < M)
                ra[l] = reinterpret_cast<const float4*>(X)[(size_t)gr * 32 + kc * 4 + q4];
            rb[l] = reinterpret_cast<const float4*>(W)[(size_t)kc * 512 + i];
        }
    };
    auto sts = [&](int buf) {
#pragma unroll
        for (int l = 0; l < 2; l++) {
            int i = tid + l * 256;
            int r = i & 127, q4 = i >> 7;
            As[buf][q4 * 4 + 0][r] = ra[l].x;
            As[buf][q4 * 4 + 1][r] = ra[l].y;
            As[buf][q4 * 4 + 2][r] = ra[l].z;
            As[buf][q4 * 4 + 3][r] = ra[l].w;
            reinterpret_cast<float4*>(&Bs[buf][0][0])[i] = rb[l];
        }
    };

    ldg(0);
    sts(0);
    ldg(1);
    __syncthreads();

    for (int kc = 0; kc < 8; kc++) {
        const int cur = kc & 1;
        if (kc + 1 < 8) sts((kc + 1) & 1);
        if (kc + 2 < 8) ldg(kc + 2);
#pragma unroll
        for (int k = 0; k < 16; k++) {
            ulonglong2 a01 = *reinterpret_cast<const ulonglong2*>(&As[cur][k][r0]);
            ulonglong2 a23 = *reinterpret_cast<const ulonglong2*>(&As[cur][k][r0 + 4]);
            float4 bl = *reinterpret_cast<const float4*>(&Bs[cur][k][c0]);
            float4 bh = *reinterpret_cast<const float4*>(&Bs[cur][k][c0 + 4]);
            u64 ap[4] = {a01.x, a01.y, a23.x, a23.y};
            u64 bb[8];
            DUP2(bb[0], bl.x); DUP2(bb[1], bl.y); DUP2(bb[2], bl.z); DUP2(bb[3], bl.w);
            DUP2(bb[4], bh.x); DUP2(bb[5], bh.y); DUP2(bb[6], bh.z); DUP2(bb[7], bh.w);
#pragma unroll
            for (int rp = 0; rp < 4; rp++)
#pragma unroll
                for (int j = 0; j < 8; j++) FMA2(acc[rp][j], ap[rp], bb[j]);
        }
        __syncthreads();
    }

#pragma unroll
    for (int rp = 0; rp < 4; rp++) {
        int gre = row0 + r0 + 2 * rp;
        float2 p[8];
#pragma unroll
        for (int j = 0; j < 8; j++) p[j] = u64_as_f2(acc[rp][j]);
#pragma unroll
        for (int h = 0; h < 2; h++) {
            int gr = gre + h;
            if (gr >= M) break;
            float4 v0, v1;
            if (h == 0) {
                v0 = make_float4(p[0].x, p[1].x, p[2].x, p[3].x);
                v1 = make_float4(p[4].x, p[5].x, p[6].x, p[7].x);
            } else {
                v0 = make_float4(p[0].y, p[1].y, p[2].y, p[3].y);
                v1 = make_float4(p[4].y, p[5].y, p[6].y, p[7].y);
            }
            __half2 hh[4];
            hh[0] = __floats2half2_rn(v0.x, v0.y);
            hh[1] = __floats2half2_rn(v0.z, v0.w);
            hh[2] = __floats2half2_rn(v1.x, v1.y);
            hh[3] = __floats2half2_rn(v1.z, v1.w);
            *reinterpret_cast<uint4*>(&g_hs1[(size_t)gr * 128 + c0]) =
                *reinterpret_cast<const uint4*>(hh);
        }
    }
}

// ---------------------------------------------------------------------------
// Edge aggregate 1 + activation:
//   h1[d] = relu(dinv[d]*(dinv[d]*hs1[d] + sum dinv[s]*hs1[s]) + b1), fp16.
// Warp per 16-node bucket, 8-wide unrolled gather, packed edge words.
// ---------------------------------------------------------------------------
__global__ __launch_bounds__(128) void k_edge1(const float* __restrict__ B1,
                                               int n, int nb) {
    __shared__ __align__(16) float acc[4][16][128];

    const int w = threadIdx.x >> 5;
    const int l4 = (threadIdx.x & 31) * 4;
    const int b = blockIdx.x * 4 + w;
    if (b >= nb) return;
    const int n0 = b * 16;

#pragma unroll
    for (int r = 0; r < 16; r++) {
        int node = n0 + r;
        float4 v = make_float4(0.f, 0.f, 0.f, 0.f);
        if (node < n) {
            uint2 u = *reinterpret_cast<const uint2*>(&g_hs1[(size_t)node * 128 + l4]);
            float2 f0 = __half22float2(*reinterpret_cast<const __half2*>(&u.x));
            float2 f1 = __half22float2(*reinterpret_cast<const __half2*>(&u.y));
            float dv = g_dinv[node];
            v = make_float4(f0.x * dv, f0.y * dv, f1.x * dv, f1.y * dv);
        }
        *reinterpret_cast<float4*>(&acc[w][r][l4]) = v;
    }

    int e = g_bstart[b];
    const int e1 = g_bstart[b + 1];
    for (; e + 7 < e1; e += 8) {
        int pk[8];
#pragma unroll
        for (int j = 0; j < 8; j++) pk[j] = g_epack[e + j];
        uint2 uu[8];
        float dv[8];
#pragma unroll
        for (int j = 0; j < 8; j++) {
            int s = pk[j] & 0x1FFFF;
            uu[j] = *reinterpret_cast<const uint2*>(&g_hs1[(size_t)s * 128 + l4]);
            dv[j] = g_dinv[s];
        }
#pragma unroll
        for (int j = 0; j < 8; j++) {
            float2 f0 = __half22float2(*reinterpret_cast<const __half2*>(&uu[j].x));
            float2 f1 = __half22float2(*reinterpret_cast<const __half2*>(&uu[j].y));
            float4* a = reinterpret_cast<float4*>(&acc[w][pk[j] >> 17][l4]);
            float4 o = *a;
            o.x = fmaf(dv[j], f0.x, o.x);
            o.y = fmaf(dv[j], f0.y, o.y);
            o.z = fmaf(dv[j], f1.x, o.z);
            o.w = fmaf(dv[j], f1.y, o.w);
            *a = o;
        }
    }
    for (; e < e1; e++) {
        int pk = g_epack[e];
        int s = pk & 0x1FFFF;
        uint2 u = *reinterpret_cast<const uint2*>(&g_hs1[(size_t)s * 128 + l4]);
        float2 f0 = __half22float2(*reinterpret_cast<const __half2*>(&u.x));
        float2 f1 = __half22float2(*reinterpret_cast<const __half2*>(&u.y));
        float dv = g_dinv[s];
        float4* a = reinterpret_cast<float4*>(&acc[w][pk >> 17][l4]);
        float4 o = *a;
        o.x = fmaf(dv, f0.x, o.x);
        o.y = fmaf(dv, f0.y, o.y);
        o.z = fmaf(dv, f1.x, o.z);
        o.w = fmaf(dv, f1.y, o.w);
        *a = o;
    }

    const float4 bb = *reinterpret_cast<const float4*>(&B1[l4]);
#pragma unroll
    for (int r = 0; r < 16; r++) {
        int node = n0 + r;
        if (node < n) {
            float dv = g_dinv[node];
            float4 o = *reinterpret_cast<const float4*>(&acc[w][r][l4]);
            o.x = fmaxf(fmaf(dv, o.x, bb.x), 0.f);
            o.y = fmaxf(fmaf(dv, o.y, bb.y), 0.f);
            o.z = fmaxf(fmaf(dv, o.z, bb.z), 0.f);
            o.w = fmaxf(fmaf(dv, o.w, bb.w), 0.f);
            __half2 hh[2];
            hh[0] = __floats2half2_rn(o.x, o.y);
            hh[1] = __floats2half2_rn(o.z, o.w);
            *reinterpret_cast<uint2*>(&g_h1[(size_t)node * 128 + l4]) =
                *reinterpret_cast<const uint2*>(hh);
        }
    }
}

// ---------------------------------------------------------------------------
// GEMM2 (fp32 compute, fp16 A-loads): hs2 = dinv[r]*(h1 @ W2), stored fp16.
// Block 64x64, 256 threads, thread tile 4x4 (frozen R10 shape).
// ---------------------------------------------------------------------------
__global__ __launch_bounds__(256) void k_gemm2(const float* __restrict__ W2,
                                               int M) {
    __shared__ float As[64][33];
    __shared__ float Bs[32][64];

    const int tid = threadIdx.x;
    const int row0 = blockIdx.x * 64;
    const int tx = tid & 15, ty = tid >> 4;
    const int r0 = ty * 4, c0 = tx * 4;

    float acc[4][4];
#pragma unroll
    for (int i = 0; i < 4; i++)
#pragma unroll
        for (int j = 0; j < 4; j++) acc[i][j] = 0.f;

    for (int kc = 0; kc < 4; kc++) {
#pragma unroll
        for (int l = 0; l < 2; l++) {
            int i = tid + l * 256;
            int r = i >> 3, q = i & 7;
            int gr = row0 + r;
            float4 v = make_float4(0.f, 0.f, 0.f, 0.f);
            if (gr < M) {
                uint2 u = *reinterpret_cast<const uint2*>(
                    &g_h1[(size_t)gr * 128 + kc * 32 + q * 4]);
                float2 f0 = __half22float2(*reinterpret_cast<const __half2*>(&u.x));
                float2 f1 = __half22float2(*reinterpret_cast<const __half2*>(&u.y));
                v = make_float4(f0.x, f0.y, f1.x, f1.y);
            }
            As[r][q * 4 + 0] = v.x;
            As[r][q * 4 + 1] = v.y;
            As[r][q * 4 + 2] = v.z;
            As[r][q * 4 + 3] = v.w;
        }
#pragma unroll
        for (int l = 0; l < 2; l++) {
            int i = tid + l * 256;
            reinterpret_cast<float4*>(&Bs[0][0])[i] =
                reinterpret_cast<const float4*>(W2 + (size_t)kc * 32 * 64)[i];
        }
        __syncthreads();

#pragma unroll
        for (int k = 0; k < 32; k++) {
            float a[4];
#pragma unroll
            for (int i = 0; i < 4; i++) a[i] = As[r0 + i][k];
            float4 b4 = *reinterpret_cast<float4*>(&Bs[k][c0]);
            float b[4] = {b4.x, b4.y, b4.z, b4.w};
#pragma unroll
            for (int i = 0; i < 4; i++)
#pragma unroll
                for (int j = 0; j < 4; j++) acc[i][j] = fmaf(a[i], b[j], acc[i][j]);
        }
        __syncthreads();
    }

#pragma unroll
    for (int i = 0; i < 4; i++) {
        int gr = row0 + r0 + i;
        if (gr >= M) break;
        float dv = g_dinv[gr];
        __half2 hh[2];
        hh[0] = __floats2half2_rn(acc[i][0] * dv, acc[i][1] * dv);
        hh[1] = __floats2half2_rn(acc[i][2] * dv, acc[i][3] * dv);
        *reinterpret_cast<uint2*>(&g_hs2[(size_t)gr * 64 + c0]) =
            *reinterpret_cast<const uint2*>(hh);
    }
}

// ---------------------------------------------------------------------------
// Edge aggregate 2 + final: OUT[d] = dinv[d]*(hs2[d]+sum hs2[src]) + b2.
// Warp per 16-node bucket, 8-wide unrolled gather, packed edge words.
// ---------------------------------------------------------------------------
__global__ __launch_bounds__(128) void k_edge2(float* __restrict__ OUT,
                                               const float* __restrict__ B2,
                                               int n, int nb) {
    __shared__ __align__(8) float acc[4][16][64];

    const int w = threadIdx.x >> 5;
    const int l2 = (threadIdx.x & 31) * 2;
    const int b = blockIdx.x * 4 + w;
    if (b >= nb) return;
    const int n0 = b * 16;

#pragma unroll
    for (int r = 0; r < 16; r++) {
        int node = n0 + r;
        float2 v = make_float2(0.f, 0.f);
        if (node < n)
            v = __half22float2(
                *reinterpret_cast<const __half2*>(&g_hs2[(size_t)node * 64 + l2]));
        *reinterpret_cast<float2*>(&acc[w][r][l2]) = v;
    }

    int e = g_bstart[b];
    const int e1 = g_bstart[b + 1];
    for (; e + 7 < e1; e += 8) {
        int pk[8];
#pragma unroll
        for (int j = 0; j < 8; j++) pk[j] = g_epack[e + j];
        uint32_t uu[8];
#pragma unroll
        for (int j = 0; j < 8; j++) {
            int s = pk[j] & 0x1FFFF;
            uu[j] = *reinterpret_cast<const uint32_t*>(&g_hs2[(size_t)s * 64 + l2]);
        }
#pragma unroll
        for (int j = 0; j < 8; j++) {
            float2 f = __half22float2(*reinterpret_cast<const __half2*>(&uu[j]));
            float2* a = reinterpret_cast<float2*>(&acc[w][pk[j] >> 17][l2]);
            float2 o = *a;
            o.x += f.x;
            o.y += f.y;
            *a = o;
        }
    }
    for (; e < e1; e++) {
        int pk = g_epack[e];
        int s = pk & 0x1FFFF;
        float2 f = __half22float2(
            *reinterpret_cast<const __half2*>(&g_hs2[(size_t)s * 64 + l2]));
        float2* a = reinterpret_cast<float2*>(&acc[w][pk >> 17][l2]);
        float2 o = *a;
        o.x += f.x;
        o.y += f.y;
        *a = o;
    }

    float2 bb = *reinterpret_cast<const float2*>(&B2[l2]);
#pragma unroll
    for (int r = 0; r < 16; r++) {
        int node = n0 + r;
        if (node < n) {
            float dv = g_dinv[node];
            float2 o = *reinterpret_cast<const float2*>(&acc[w][r][l2]);
            o.x = fmaf(dv, o.x, bb.x);
            o.y = fmaf(dv, o.y, bb.y);
            *reinterpret_cast<float2*>(&OUT[(size_t)node * 64 + l2]) = o;
        }
    }
}

// ---------------------------------------------------------------------------
extern "C" void kernel_launch(void* const* d_in, const int* in_sizes, int n_in,
                              void* d_out, int out_size) {
    const float* x  = (const float*)d_in[0];
    const int*   ei = (const int*)d_in[1];
    const float* W1 = (const float*)d_in[2];
    const float* b1 = (const float*)d_in[3];
    const float* W2 = (const float*)d_in[4];
    const float* b2 = (const float*)d_in[5];
    float* out = (float*)d_out;

    const int N = in_sizes[0] / 128;
    const int E = in_sizes[1] / 2;
    const int NB = (N + 15) / 16;
    const int* src = ei;
    const int* dst = ei + E;

    static cudaStream_t side = nullptr;
    static cudaEvent_t evA = nullptr, evB = nullptr;
    if (!side) {
        cudaStreamCreateWithFlags(&side, cudaStreamNonBlocking);
        cudaEventCreateWithFlags(&evA, cudaEventDisableTiming);
        cudaEventCreateWithFlags(&evB, cudaEventDisableTiming);
    }

    // Fork: preprocessing on side stream, GEMM1 (independent) on main stream.
    cudaEventRecord(evA, 0);
    cudaStreamWaitEvent(side, evA, 0);

    int mx = (N > NB) ? N : NB;
    k_init<<<(mx + 255) / 256, 256, 0, side>>>(N, NB);
    k_count<<<(E + 255) / 256, 256, 0, side>>>(dst, E);
    k_dinv<<<(N + 255) / 256, 256, 0, side>>>(N);
    k_scan<<<1, 1024, 0, side>>>(NB);
    k_sort<<<(E + 255) / 256, 256, 0, side>>>(src, dst, E);
    cudaEventRecord(evB, side);

    k_gemm1<<<(N + 127) / 128, 256>>>(x, W1, N);

    // Join: edge1 needs both GEMM1 output and sorted edges + dinv.
    cudaStreamWaitEvent(0, evB, 0);

    k_edge1<<<(NB + 3) / 4, 128>>>(b1, N, NB);
    k_gemm2<<<(N + 63) / 64, 256>>>(W2, N);
    k_edge2<<<(NB + 3) / 4, 128>>>(out, b2, N, NB);
}